// round 8
// baseline (speedup 1.0000x reference)
#include <cuda_runtime.h>
#include <cuda_bf16.h>
#include <cstdint>
#include <cstdio>

// Problem shape (fixed for this registry entry)
#define DIMC 2048
#define HID  8192
#define BSZ  4
#define SEQ  2048
#define MROWS (BSZ*SEQ)   // 8192 rows (B*T)

// ---------------------------------------------------------------------------
// Device scratch (static allocation; no cudaMalloc allowed)
// ---------------------------------------------------------------------------
__device__ float   g_kact[(size_t)MROWS * HID];   // relu(K)^2, fp32
__device__ int8_t  g_kq  [(size_t)MROWS * HID];   // quantized k activations (s8)
__device__ int8_t  g_xkq [(size_t)MROWS * DIMC];  // quantized LN(xk) (s8)
__device__ int8_t  g_xrq [(size_t)MROWS * DIMC];  // quantized LN(xr) (s8)
__device__ int8_t  g_wkq [(size_t)HID  * DIMC];   // ternary wk (s8)
__device__ int8_t  g_wrq [(size_t)DIMC * DIMC];   // ternary wr (s8)
__device__ int8_t  g_wvq [(size_t)DIMC * HID];    // ternary wv (s8)
__device__ float   g_rg  [(size_t)MROWS * DIMC];  // sigmoid gate
__device__ float   g_sk[MROWS], g_sr[MROWS], g_sv[MROWS]; // per-row act scales
__device__ float   g_part[1536];                  // reduction partials (3 x 512)
__device__ float   g_wscale[3];                   // weight scales (wk, wr, wv)

// ---------------------------------------------------------------------------
// Helpers
// ---------------------------------------------------------------------------
__device__ __forceinline__ float block_sum256(float v) {
    __shared__ float sh[8];
    int lane = threadIdx.x & 31, wid = threadIdx.x >> 5;
#pragma unroll
    for (int o = 16; o; o >>= 1) v += __shfl_xor_sync(0xffffffffu, v, o);
    if (lane == 0) sh[wid] = v;
    __syncthreads();
    if (wid == 0) {
        v = (lane < 8) ? sh[lane] : 0.f;
#pragma unroll
        for (int o = 4; o; o >>= 1) v += __shfl_xor_sync(0xffffffffu, v, o);
        if (lane == 0) sh[0] = v;
    }
    __syncthreads();
    v = sh[0];
    __syncthreads();   // make helper safely re-usable
    return v;
}

__device__ __forceinline__ uint32_t smem_u32(const void* p) {
    return (uint32_t)__cvta_generic_to_shared(p);
}

__device__ __forceinline__ void cp_async16(uint32_t dst, const void* src) {
    asm volatile("cp.async.cg.shared.global [%0], [%1], 16;\n" :: "r"(dst), "l"(src));
}
__device__ __forceinline__ void cp_commit() {
    asm volatile("cp.async.commit_group;\n");
}
template<int N>
__device__ __forceinline__ void cp_wait() {
    asm volatile("cp.async.wait_group %0;\n" :: "n"(N));
}

// Pack 4 floats (already rint'ed, in [-127,127]) into 4 s8 lanes of a u32.
__device__ __forceinline__ uint32_t pack_s8x4(float q0, float q1, float q2, float q3) {
    int i0 = (int)q0, i1 = (int)q1, i2 = (int)q2, i3 = (int)q3;
    return (uint32_t)(i0 & 0xFF) | ((uint32_t)(i1 & 0xFF) << 8) |
           ((uint32_t)(i2 & 0xFF) << 16) | ((uint32_t)(i3 & 0xFF) << 24);
}

// ---------------------------------------------------------------------------
// Weight-scale reduction (deterministic two-pass, no float atomics)
// ---------------------------------------------------------------------------
__global__ void abssum_kernel(const float* __restrict__ w, int n, float* __restrict__ out) {
    const float4* w4 = (const float4*)w;
    int n4 = n >> 2;
    float s = 0.f;
    for (int i = blockIdx.x * 256 + threadIdx.x; i < n4; i += gridDim.x * 256) {
        float4 v = w4[i];
        s += fabsf(v.x) + fabsf(v.y) + fabsf(v.z) + fabsf(v.w);
    }
    s = block_sum256(s);
    if (threadIdx.x == 0) out[blockIdx.x] = s;
}

__global__ void wscale_fin_kernel() {
    const float ninv0 = 1.f / ((float)HID * (float)DIMC);
    const float ninv1 = 1.f / ((float)DIMC * (float)DIMC);
    const float ninv2 = 1.f / ((float)DIMC * (float)HID);
    float ninv[3] = {ninv0, ninv1, ninv2};
    for (int j = 0; j < 3; j++) {
        float s = 0.f;
        for (int i = threadIdx.x; i < 512; i += 256) s += g_part[j * 512 + i];
        s = block_sum256(s);
        if (threadIdx.x == 0) g_wscale[j] = fmaxf(s * ninv[j], 1e-8f);
    }
}

// Ternary weight quantization: wq = round(clip(w/scale, -1, 1)) in {-1,0,1} -> s8
__global__ void wquant_kernel(const float* __restrict__ w, int8_t* __restrict__ wq,
                              int sidx, int n) {
    float inv = 1.f / g_wscale[sidx];
    const float4* w4 = (const float4*)w;
    uint32_t* q4 = (uint32_t*)wq;
    int n4 = n >> 2;
    for (int i = blockIdx.x * blockDim.x + threadIdx.x; i < n4; i += gridDim.x * blockDim.x) {
        float4 v = w4[i];
        float q0 = rintf(fminf(fmaxf(v.x * inv, -1.f), 1.f));
        float q1 = rintf(fminf(fmaxf(v.y * inv, -1.f), 1.f));
        float q2 = rintf(fminf(fmaxf(v.z * inv, -1.f), 1.f));
        float q3 = rintf(fminf(fmaxf(v.w * inv, -1.f), 1.f));
        q4[i] = pack_s8x4(q0, q1, q2, q3);
    }
}

// ---------------------------------------------------------------------------
// Fused token-shift + LayerNorm + act-quant for the xk / xr paths (s8 out)
// ---------------------------------------------------------------------------
__global__ __launch_bounds__(256) void act_prep_kernel(
    const float* __restrict__ x,
    const float* __restrict__ mu_k, const float* __restrict__ mu_r,
    const float* __restrict__ gk, const float* __restrict__ bk,
    const float* __restrict__ gr, const float* __restrict__ br)
{
    __shared__ __align__(16) float sxk[DIMC];
    __shared__ __align__(16) float sxr[DIMC];
    int row = blockIdx.x;
    int t   = row % SEQ;
    int tid = threadIdx.x;
    const float4* xr4 = (const float4*)(x + (size_t)row * DIMC);
    const float4* xp4 = xr4 - DIMC / 4;           // valid only when t > 0
    const float4* muk4 = (const float4*)mu_k;
    const float4* mur4 = (const float4*)mu_r;
    const float4* gk4 = (const float4*)gk;
    const float4* bk4 = (const float4*)bk;
    const float4* gr4 = (const float4*)gr;
    const float4* br4 = (const float4*)br;
    float4* sxk4 = (float4*)sxk;
    float4* sxr4 = (float4*)sxr;
    const int N4 = DIMC / 4;   // 512

    float sk = 0.f, sr = 0.f;
#pragma unroll
    for (int i = tid; i < N4; i += 256) {
        float4 xv = xr4[i];
        float4 pv = (t == 0) ? make_float4(0.f, 0.f, 0.f, 0.f) : xp4[i];
        float4 mk4v = muk4[i], mr4v = mur4[i];
        float4 a, b;
        a.x = xv.x + (pv.x - xv.x) * mk4v.x;  b.x = xv.x + (pv.x - xv.x) * mr4v.x;
        a.y = xv.y + (pv.y - xv.y) * mk4v.y;  b.y = xv.y + (pv.y - xv.y) * mr4v.y;
        a.z = xv.z + (pv.z - xv.z) * mk4v.z;  b.z = xv.z + (pv.z - xv.z) * mr4v.z;
        a.w = xv.w + (pv.w - xv.w) * mk4v.w;  b.w = xv.w + (pv.w - xv.w) * mr4v.w;
        sxk4[i] = a; sxr4[i] = b;
        sk += (a.x + a.y) + (a.z + a.w);
        sr += (b.x + b.y) + (b.z + b.w);
    }
    float mk = block_sum256(sk) * (1.f / DIMC);
    float mr = block_sum256(sr) * (1.f / DIMC);

    float vk = 0.f, vr = 0.f;
#pragma unroll
    for (int i = tid; i < N4; i += 256) {
        float4 a = sxk4[i], b = sxr4[i];
        float a0 = a.x - mk, a1 = a.y - mk, a2 = a.z - mk, a3 = a.w - mk;
        float b0 = b.x - mr, b1 = b.y - mr, b2 = b.z - mr, b3 = b.w - mr;
        vk += (a0 * a0 + a1 * a1) + (a2 * a2 + a3 * a3);
        vr += (b0 * b0 + b1 * b1) + (b2 * b2 + b3 * b3);
    }
    vk = block_sum256(vk) * (1.f / DIMC);
    vr = block_sum256(vr) * (1.f / DIMC);
    float rk  = rsqrtf(vk + 1e-5f);
    float rr_ = rsqrtf(vr + 1e-5f);

    float ak = 0.f, ar = 0.f;
#pragma unroll
    for (int i = tid; i < N4; i += 256) {
        float4 a = sxk4[i], b = sxr4[i];
        float4 g1 = gk4[i], b1 = bk4[i], g2 = gr4[i], b2 = br4[i];
        float4 oa, ob;
        oa.x = (a.x - mk) * rk * g1.x + b1.x;   ob.x = (b.x - mr) * rr_ * g2.x + b2.x;
        oa.y = (a.y - mk) * rk * g1.y + b1.y;   ob.y = (b.y - mr) * rr_ * g2.y + b2.y;
        oa.z = (a.z - mk) * rk * g1.z + b1.z;   ob.z = (b.z - mr) * rr_ * g2.z + b2.z;
        oa.w = (a.w - mk) * rk * g1.w + b1.w;   ob.w = (b.w - mr) * rr_ * g2.w + b2.w;
        sxk4[i] = oa; sxr4[i] = ob;
        ak += (fabsf(oa.x) + fabsf(oa.y)) + (fabsf(oa.z) + fabsf(oa.w));
        ar += (fabsf(ob.x) + fabsf(ob.y)) + (fabsf(ob.z) + fabsf(ob.w));
    }
    float msk = block_sum256(ak) * (1.f / DIMC);
    float msr = block_sum256(ar) * (1.f / DIMC);
    float sclk = fmaxf(msk, 1e-8f) * (2.5f / 127.f);
    float sclr = fmaxf(msr, 1e-8f) * (2.5f / 127.f);

    float isclk = 1.f / sclk, isclr = 1.f / sclr;
    uint32_t* outk = (uint32_t*)(g_xkq + (size_t)row * DIMC);
    uint32_t* outr = (uint32_t*)(g_xrq + (size_t)row * DIMC);
#pragma unroll
    for (int i = tid; i < N4; i += 256) {
        float4 a = sxk4[i], b = sxr4[i];
        float qa0 = rintf(fminf(fmaxf(a.x * isclk, -127.f), 127.f));
        float qa1 = rintf(fminf(fmaxf(a.y * isclk, -127.f), 127.f));
        float qa2 = rintf(fminf(fmaxf(a.z * isclk, -127.f), 127.f));
        float qa3 = rintf(fminf(fmaxf(a.w * isclk, -127.f), 127.f));
        float qb0 = rintf(fminf(fmaxf(b.x * isclr, -127.f), 127.f));
        float qb1 = rintf(fminf(fmaxf(b.y * isclr, -127.f), 127.f));
        float qb2 = rintf(fminf(fmaxf(b.z * isclr, -127.f), 127.f));
        float qb3 = rintf(fminf(fmaxf(b.w * isclr, -127.f), 127.f));
        outk[i] = pack_s8x4(qa0, qa1, qa2, qa3);
        outr[i] = pack_s8x4(qb0, qb1, qb2, qb3);
    }
    if (tid == 0) { g_sk[row] = sclk; g_sr[row] = sclr; }
}

// ---------------------------------------------------------------------------
// LayerNorm + act-quant for k_act rows (H = 8192, row in dynamic SMEM, s8 out)
// ---------------------------------------------------------------------------
__global__ __launch_bounds__(256) void kact_ln_kernel(
    const float* __restrict__ gv, const float* __restrict__ bv)
{
    extern __shared__ __align__(16) float srow[];   // HID floats = 32 KB
    int row = blockIdx.x;
    int tid = threadIdx.x;
    const float4* in4 = (const float4*)(g_kact + (size_t)row * HID);
    float4* srow4 = (float4*)srow;
    const float4* gv4 = (const float4*)gv;
    const float4* bv4 = (const float4*)bv;
    const int N4 = HID / 4;   // 2048

    float s = 0.f;
#pragma unroll
    for (int i = tid; i < N4; i += 256) {
        float4 v = in4[i];
        srow4[i] = v;
        s += (v.x + v.y) + (v.z + v.w);
    }
    float mu = block_sum256(s) * (1.f / HID);

    float vs = 0.f;
#pragma unroll
    for (int i = tid; i < N4; i += 256) {
        float4 v = srow4[i];
        float a0 = v.x - mu, a1 = v.y - mu, a2 = v.z - mu, a3 = v.w - mu;
        vs += (a0 * a0 + a1 * a1) + (a2 * a2 + a3 * a3);
    }
    float var = block_sum256(vs) * (1.f / HID);
    float rstd = rsqrtf(var + 1e-5f);

    float asum = 0.f;
#pragma unroll
    for (int i = tid; i < N4; i += 256) {
        float4 v = srow4[i];
        float4 g = gv4[i];
        float4 b = bv4[i];
        float4 a;
        a.x = (v.x - mu) * rstd * g.x + b.x;
        a.y = (v.y - mu) * rstd * g.y + b.y;
        a.z = (v.z - mu) * rstd * g.z + b.z;
        a.w = (v.w - mu) * rstd * g.w + b.w;
        srow4[i] = a;
        asum += (fabsf(a.x) + fabsf(a.y)) + (fabsf(a.z) + fabsf(a.w));
    }
    float ma = block_sum256(asum) * (1.f / HID);
    float scl = fmaxf(ma, 1e-8f) * (2.5f / 127.f);

    float iscl = 1.f / scl;
    uint32_t* out = (uint32_t*)(g_kq + (size_t)row * HID);
#pragma unroll
    for (int i = tid; i < N4; i += 256) {
        float4 a = srow4[i];
        float q0 = rintf(fminf(fmaxf(a.x * iscl, -127.f), 127.f));
        float q1 = rintf(fminf(fmaxf(a.y * iscl, -127.f), 127.f));
        float q2 = rintf(fminf(fmaxf(a.z * iscl, -127.f), 127.f));
        float q3 = rintf(fminf(fmaxf(a.w * iscl, -127.f), 127.f));
        out[i] = pack_s8x4(q0, q1, q2, q3);
    }
    if (tid == 0) g_sv[row] = scl;
}

// ---------------------------------------------------------------------------
// Tiled s8 IMMA GEMM (mma.sync.m16n8k32.s8) with 4-stage cp.async pipeline.
//   C[m,n] = (sum_k A[m,k]*B[n,k]) * scaleA[m] * (*wsc), fused epilogue
// BM=BN=128, BK=32 (s8), 256 threads (8 warps, 2x4 grid, warp = 64x32).
// SMEM row stride 48 B -> conflict-free for both STS.128 and ldmatrix.
// Epilogues: 0 = relu^2 (kact), 1 = sigmoid (gate), 2 = rg * val (output)
// ---------------------------------------------------------------------------
#define BMT 128
#define BNT 128
#define BKT 32
#define SST 48      // padded SMEM row stride in BYTES (s8 elems)
#define STAGES 4

template<int EPI>
__global__ __launch_bounds__(256) void gemm_kernel(
    const int8_t* __restrict__ A,     // [M, K] row-major s8
    const int8_t* __restrict__ Bm,    // [N, K] row-major s8 (K-major weights)
    const float* __restrict__ scaleA, // [M]
    const float* __restrict__ wsc,    // pointer to scalar weight scale
    const float* __restrict__ rg,     // gate (EPI==2 only)
    float* __restrict__ C,            // [M, ldc]
    int K, int ldc)
{
    extern __shared__ __align__(16) int8_t smem[];
    int8_t* As = smem;                          // STAGES * BMT * SST
    int8_t* Bs = smem + STAGES * BMT * SST;     // STAGES * BNT * SST

    int tid  = threadIdx.x;
    int m0   = blockIdx.y * BMT;
    int n0   = blockIdx.x * BNT;
    int warp = tid >> 5, lane = tid & 31;
    int wm = warp >> 2;      // 0..1
    int wn = warp & 3;       // 0..3

    int acc[4][4][4];
#pragma unroll
    for (int i = 0; i < 4; i++)
#pragma unroll
        for (int j = 0; j < 4; j++)
#pragma unroll
            for (int e = 0; e < 4; e++) acc[i][j][e] = 0;

    // global->shared: thread covers 16 contiguous s8 of one row (half a 32B row)
    int lr = tid >> 1;            // 0..127
    int lc = (tid & 1) * 16;      // 0 or 16
    const int8_t* Ag = A  + (size_t)(m0 + lr) * K + lc;
    const int8_t* Bg = Bm + (size_t)(n0 + lr) * K + lc;
    uint32_t AsW = smem_u32(As + lr * SST + lc);
    uint32_t BsW = smem_u32(Bs + lr * SST + lc);
    const uint32_t stageBytes = BMT * SST;   // 6144

    int KT = K / BKT;

    // --- prologue: prefetch STAGES-1 tiles ---
#pragma unroll
    for (int s = 0; s < STAGES - 1; s++) {
        int k0 = s * BKT;
        cp_async16(AsW + s * stageBytes, Ag + k0);
        cp_async16(BsW + s * stageBytes, Bg + k0);
        cp_commit();
    }

    int qr = lane & 7;
    int qg = lane >> 3;
    int l4 = lane & 15;

    for (int kt = 0; kt < KT; kt++) {
        cp_wait<STAGES - 2>();      // tile kt resident
        __syncthreads();            // all warps done with buffer (kt-1)%STAGES

        int lt = kt + STAGES - 1;
        if (lt < KT) {
            int bufi = lt % STAGES;
            int k0 = lt * BKT;
            cp_async16(AsW + bufi * stageBytes, Ag + k0);
            cp_async16(BsW + bufi * stageBytes, Bg + k0);
        }
        cp_commit();

        const int8_t* Asb = As + (kt % STAGES) * stageBytes;
        const int8_t* Bsb = Bs + (kt % STAGES) * stageBytes;

        uint32_t af[4][4];
        uint32_t bf[4][2];
#pragma unroll
        for (int mi = 0; mi < 4; mi++) {
            int r = wm * 64 + mi * 16 + qr + (qg & 1) * 8;
            int c = (qg >> 1) * 16;
            uint32_t addr = smem_u32(&Asb[r * SST + c]);
            asm volatile(
                "ldmatrix.sync.aligned.m8n8.x4.shared.b16 {%0,%1,%2,%3}, [%4];"
                : "=r"(af[mi][0]), "=r"(af[mi][1]), "=r"(af[mi][2]), "=r"(af[mi][3])
                : "r"(addr));
        }
#pragma unroll
        for (int ni = 0; ni < 4; ni++) {
            int r = wn * 32 + ni * 8 + (l4 & 7);
            int c = (l4 >> 3) * 16;
            uint32_t addr = smem_u32(&Bsb[r * SST + c]);
            asm volatile(
                "ldmatrix.sync.aligned.m8n8.x2.shared.b16 {%0,%1}, [%2];"
                : "=r"(bf[ni][0]), "=r"(bf[ni][1])
                : "r"(addr));
        }
#pragma unroll
        for (int mi = 0; mi < 4; mi++)
#pragma unroll
            for (int ni = 0; ni < 4; ni++) {
                asm volatile(
                    "mma.sync.aligned.m16n8k32.row.col.s32.s8.s8.s32 "
                    "{%0,%1,%2,%3}, {%4,%5,%6,%7}, {%8,%9}, {%0,%1,%2,%3};"
                    : "+r"(acc[mi][ni][0]), "+r"(acc[mi][ni][1]),
                      "+r"(acc[mi][ni][2]), "+r"(acc[mi][ni][3])
                    : "r"(af[mi][0]), "r"(af[mi][1]), "r"(af[mi][2]), "r"(af[mi][3]),
                      "r"(bf[ni][0]), "r"(bf[ni][1]));
            }
    }
    cp_wait<0>();   // drain trailing empty groups

    // ---- fused epilogue ----
    float sw = *wsc;
    int rbase = m0 + wm * 64 + (lane >> 2);
    int cbase = n0 + wn * 32 + (lane & 3) * 2;
#pragma unroll
    for (int mi = 0; mi < 4; mi++) {
        int r0_ = rbase + mi * 16;
        float sA0 = scaleA[r0_]     * sw;
        float sA1 = scaleA[r0_ + 8] * sw;
#pragma unroll
        for (int ni = 0; ni < 4; ni++) {
            int c = cbase + ni * 8;
#pragma unroll
            for (int half = 0; half < 2; half++) {
                int rr = r0_ + half * 8;
                float sA = half ? sA1 : sA0;
                float v0 = (float)acc[mi][ni][half * 2 + 0] * sA;
                float v1 = (float)acc[mi][ni][half * 2 + 1] * sA;
                float2 ov;
                if (EPI == 0) {
                    float t0 = fmaxf(v0, 0.f), t1 = fmaxf(v1, 0.f);
                    ov.x = t0 * t0; ov.y = t1 * t1;
                } else if (EPI == 1) {
                    ov.x = 1.f / (1.f + expf(-v0));
                    ov.y = 1.f / (1.f + expf(-v1));
                } else {
                    float2 g2 = *(const float2*)(rg + (size_t)rr * ldc + c);
                    ov.x = g2.x * v0; ov.y = g2.y * v1;
                }
                *(float2*)(C + (size_t)rr * ldc + c) = ov;
            }
        }
    }
}

// ---------------------------------------------------------------------------
// Final state: x[:, -1, :]
// ---------------------------------------------------------------------------
__global__ void state_copy_kernel(const float* __restrict__ x, float* __restrict__ out) {
    int i = blockIdx.x * 256 + threadIdx.x;
    if (i < BSZ * DIMC) {
        int b = i / DIMC, d = i % DIMC;
        out[i] = x[((size_t)b * SEQ + (SEQ - 1)) * DIMC + d];
    }
}

// ---------------------------------------------------------------------------
// Host launcher (graph-capturable: kernel launches only)
// ---------------------------------------------------------------------------
extern "C" void kernel_launch(void* const* d_in, const int* in_sizes, int n_in,
                              void* d_out, int out_size) {
    (void)in_sizes; (void)n_in;
    const float* x    = (const float*)d_in[0];
    const float* mu_k = (const float*)d_in[1];
    const float* mu_r = (const float*)d_in[2];
    const float* wk   = (const float*)d_in[3];
    const float* gk   = (const float*)d_in[4];
    const float* bk   = (const float*)d_in[5];
    const float* wr   = (const float*)d_in[6];
    const float* gr   = (const float*)d_in[7];
    const float* br   = (const float*)d_in[8];
    const float* wv   = (const float*)d_in[9];
    const float* gv   = (const float*)d_in[10];
    const float* bv   = (const float*)d_in[11];
    float* out = (float*)d_out;

    float *p_part, *p_wscale, *p_kact, *p_rg, *p_sk, *p_sr, *p_sv;
    int8_t *p_xkq, *p_xrq, *p_wkq, *p_wrq, *p_wvq, *p_kq;
    cudaGetSymbolAddress((void**)&p_part,   g_part);
    cudaGetSymbolAddress((void**)&p_wscale, g_wscale);
    cudaGetSymbolAddress((void**)&p_kact,   g_kact);
    cudaGetSymbolAddress((void**)&p_rg,     g_rg);
    cudaGetSymbolAddress((void**)&p_sk,     g_sk);
    cudaGetSymbolAddress((void**)&p_sr,     g_sr);
    cudaGetSymbolAddress((void**)&p_sv,     g_sv);
    cudaGetSymbolAddress((void**)&p_xkq,    g_xkq);
    cudaGetSymbolAddress((void**)&p_xrq,    g_xrq);
    cudaGetSymbolAddress((void**)&p_wkq,    g_wkq);
    cudaGetSymbolAddress((void**)&p_wrq,    g_wrq);
    cudaGetSymbolAddress((void**)&p_wvq,    g_wvq);
    cudaGetSymbolAddress((void**)&p_kq,     g_kq);

    const int smem_gemm = STAGES * (BMT + BNT) * SST;   // 49152 B
    cudaFuncSetAttribute(gemm_kernel<0>, cudaFuncAttributeMaxDynamicSharedMemorySize, smem_gemm);
    cudaFuncSetAttribute(gemm_kernel<1>, cudaFuncAttributeMaxDynamicSharedMemorySize, smem_gemm);
    cudaFuncSetAttribute(gemm_kernel<2>, cudaFuncAttributeMaxDynamicSharedMemorySize, smem_gemm);

    // 1) weight scales (deterministic two-pass)
    abssum_kernel<<<512, 256>>>(wk, HID * DIMC,  p_part);
    abssum_kernel<<<512, 256>>>(wr, DIMC * DIMC, p_part + 512);
    abssum_kernel<<<512, 256>>>(wv, DIMC * HID,  p_part + 1024);
    wscale_fin_kernel<<<1, 256>>>();

    // 2) ternary weight quantization -> s8 (vectorized)
    wquant_kernel<<<1024, 256>>>(wk, p_wkq, 0, HID * DIMC);
    wquant_kernel<<<256,  256>>>(wr, p_wrq, 1, DIMC * DIMC);
    wquant_kernel<<<1024, 256>>>(wv, p_wvq, 2, DIMC * HID);

    // 3) token-shift + LN + act-quant (xk / xr, vectorized, s8 out)
    act_prep_kernel<<<MROWS, 256>>>(x, mu_k, mu_r, gk, bk, gr, br);

    // 4) K GEMM (8192 x 8192 x 2048) with fused relu^2
    {
        dim3 g(HID / BNT, MROWS / BMT);
        gemm_kernel<0><<<g, 256, smem_gemm>>>(p_xkq, p_wkq, p_sk, p_wscale + 0,
                                              nullptr, p_kact, DIMC, HID);
    }

    // 5) LN + act-quant over k_act rows (H = 8192, vectorized, s8 out)
    kact_ln_kernel<<<MROWS, 256, HID * sizeof(float)>>>(gv, bv);

    // 6) R GEMM (8192 x 2048 x 2048) with fused sigmoid
    {
        dim3 g(DIMC / BNT, MROWS / BMT);
        gemm_kernel<1><<<g, 256, smem_gemm>>>(p_xrq, p_wrq, p_sr, p_wscale + 1,
                                              nullptr, p_rg, DIMC, DIMC);
    }

    // 7) V GEMM (8192 x 2048 x 8192) with fused gate multiply -> output
    {
        dim3 g(DIMC / BNT, MROWS / BMT);
        gemm_kernel<2><<<g, 256, smem_gemm>>>(p_kq, p_wvq, p_sv, p_wscale + 2,
                                              p_rg, out, HID, DIMC);
    }

    // 8) second output: x[:, -1, :]
    if (out_size >= MROWS * DIMC + BSZ * DIMC) {
        state_copy_kernel<<<(BSZ * DIMC + 255) / 256, 256>>>(
            x, out + (size_t)MROWS * DIMC);
    }
}

// round 17
// speedup vs baseline: 1.7363x; 1.7363x over previous
#include <cuda_runtime.h>
#include <cuda_bf16.h>
#include <cstdint>
#include <cstdio>

#define DIMC 2048
#define HID  8192
#define BSZ  4
#define SEQ  2048
#define MROWS (BSZ*SEQ)   // 8192

// ---------------------------------------------------------------------------
// Device scratch
// ---------------------------------------------------------------------------
__device__ float          g_kact[(size_t)MROWS * HID];
__device__ __nv_bfloat16  g_kq  [(size_t)MROWS * HID];
__device__ __nv_bfloat16  g_xkq [(size_t)MROWS * DIMC];
__device__ __nv_bfloat16  g_xrq [(size_t)MROWS * DIMC];
__device__ __nv_bfloat16  g_wkq [(size_t)HID  * DIMC];
__device__ __nv_bfloat16  g_wrq [(size_t)DIMC * DIMC];
__device__ __nv_bfloat16  g_wvq [(size_t)DIMC * HID];
__device__ float          g_rg  [(size_t)MROWS * DIMC];
__device__ float          g_sk[MROWS], g_sr[MROWS], g_sv[MROWS];
__device__ float          g_part[1536];
__device__ float          g_wscale[3];

// ---------------------------------------------------------------------------
// Helpers
// ---------------------------------------------------------------------------
__device__ __forceinline__ float block_sum256(float v) {
    __shared__ float sh[8];
    int lane = threadIdx.x & 31, wid = threadIdx.x >> 5;
#pragma unroll
    for (int o = 16; o; o >>= 1) v += __shfl_xor_sync(0xffffffffu, v, o);
    if (lane == 0) sh[wid] = v;
    __syncthreads();
    if (wid == 0) {
        v = (lane < 8) ? sh[lane] : 0.f;
#pragma unroll
        for (int o = 4; o; o >>= 1) v += __shfl_xor_sync(0xffffffffu, v, o);
        if (lane == 0) sh[0] = v;
    }
    __syncthreads();
    v = sh[0];
    __syncthreads();
    return v;
}

__device__ __forceinline__ uint32_t smem_u32(const void* p) {
    return (uint32_t)__cvta_generic_to_shared(p);
}
__device__ __forceinline__ void cp_async16(uint32_t dst, const void* src) {
    asm volatile("cp.async.cg.shared.global [%0], [%1], 16;\n" :: "r"(dst), "l"(src));
}
__device__ __forceinline__ void cp_commit() {
    asm volatile("cp.async.commit_group;\n");
}
template<int N>
__device__ __forceinline__ void cp_wait() {
    asm volatile("cp.async.wait_group %0;\n" :: "n"(N));
}

// ---------------------------------------------------------------------------
// Weight scales + ternary quant (bf16 out)
// ---------------------------------------------------------------------------
__global__ void abssum_kernel(const float* __restrict__ w, int n, float* __restrict__ out) {
    const float4* w4 = (const float4*)w;
    int n4 = n >> 2;
    float s = 0.f;
    for (int i = blockIdx.x * 256 + threadIdx.x; i < n4; i += gridDim.x * 256) {
        float4 v = w4[i];
        s += fabsf(v.x) + fabsf(v.y) + fabsf(v.z) + fabsf(v.w);
    }
    s = block_sum256(s);
    if (threadIdx.x == 0) out[blockIdx.x] = s;
}

__global__ void wscale_fin_kernel() {
    const float ninv[3] = {1.f / ((float)HID * DIMC), 1.f / ((float)DIMC * DIMC),
                           1.f / ((float)DIMC * HID)};
    for (int j = 0; j < 3; j++) {
        float s = 0.f;
        for (int i = threadIdx.x; i < 512; i += 256) s += g_part[j * 512 + i];
        s = block_sum256(s);
        if (threadIdx.x == 0) g_wscale[j] = fmaxf(s * ninv[j], 1e-8f);
    }
}

__global__ void wquant_kernel(const float* __restrict__ w, __nv_bfloat16* __restrict__ wq,
                              int sidx, int n) {
    float inv = 1.f / g_wscale[sidx];
    const float4* w4 = (const float4*)w;
    uint2* q4 = (uint2*)wq;
    int n4 = n >> 2;
    for (int i = blockIdx.x * blockDim.x + threadIdx.x; i < n4; i += gridDim.x * blockDim.x) {
        float4 v = w4[i];
        float q0 = rintf(fminf(fmaxf(v.x * inv, -1.f), 1.f));
        float q1 = rintf(fminf(fmaxf(v.y * inv, -1.f), 1.f));
        float q2 = rintf(fminf(fmaxf(v.z * inv, -1.f), 1.f));
        float q3 = rintf(fminf(fmaxf(v.w * inv, -1.f), 1.f));
        __nv_bfloat162 p0 = __floats2bfloat162_rn(q0, q1);
        __nv_bfloat162 p1 = __floats2bfloat162_rn(q2, q3);
        uint2 o; o.x = *(uint32_t*)&p0; o.y = *(uint32_t*)&p1;
        q4[i] = o;
    }
}

// ---------------------------------------------------------------------------
// Token-shift + LN + act-quant (bf16 out)
// ---------------------------------------------------------------------------
__global__ __launch_bounds__(256) void act_prep_kernel(
    const float* __restrict__ x,
    const float* __restrict__ mu_k, const float* __restrict__ mu_r,
    const float* __restrict__ gk, const float* __restrict__ bk,
    const float* __restrict__ gr, const float* __restrict__ br)
{
    __shared__ __align__(16) float sxk[DIMC];
    __shared__ __align__(16) float sxr[DIMC];
    int row = blockIdx.x;
    int t   = row % SEQ;
    int tid = threadIdx.x;
    const float4* xr4 = (const float4*)(x + (size_t)row * DIMC);
    const float4* xp4 = xr4 - DIMC / 4;
    const float4* muk4 = (const float4*)mu_k;
    const float4* mur4 = (const float4*)mu_r;
    const float4* gk4 = (const float4*)gk;
    const float4* bk4 = (const float4*)bk;
    const float4* gr4 = (const float4*)gr;
    const float4* br4 = (const float4*)br;
    float4* sxk4 = (float4*)sxk;
    float4* sxr4 = (float4*)sxr;
    const int N4 = DIMC / 4;

    float sk = 0.f, sr = 0.f;
#pragma unroll
    for (int i = tid; i < N4; i += 256) {
        float4 xv = xr4[i];
        float4 pv = (t == 0) ? make_float4(0.f, 0.f, 0.f, 0.f) : xp4[i];
        float4 mk4v = muk4[i], mr4v = mur4[i];
        float4 a, b;
        a.x = xv.x + (pv.x - xv.x) * mk4v.x;  b.x = xv.x + (pv.x - xv.x) * mr4v.x;
        a.y = xv.y + (pv.y - xv.y) * mk4v.y;  b.y = xv.y + (pv.y - xv.y) * mr4v.y;
        a.z = xv.z + (pv.z - xv.z) * mk4v.z;  b.z = xv.z + (pv.z - xv.z) * mr4v.z;
        a.w = xv.w + (pv.w - xv.w) * mk4v.w;  b.w = xv.w + (pv.w - xv.w) * mr4v.w;
        sxk4[i] = a; sxr4[i] = b;
        sk += (a.x + a.y) + (a.z + a.w);
        sr += (b.x + b.y) + (b.z + b.w);
    }
    float mk = block_sum256(sk) * (1.f / DIMC);
    float mr = block_sum256(sr) * (1.f / DIMC);

    float vk = 0.f, vr = 0.f;
#pragma unroll
    for (int i = tid; i < N4; i += 256) {
        float4 a = sxk4[i], b = sxr4[i];
        float a0 = a.x - mk, a1 = a.y - mk, a2 = a.z - mk, a3 = a.w - mk;
        float b0 = b.x - mr, b1 = b.y - mr, b2 = b.z - mr, b3 = b.w - mr;
        vk += (a0 * a0 + a1 * a1) + (a2 * a2 + a3 * a3);
        vr += (b0 * b0 + b1 * b1) + (b2 * b2 + b3 * b3);
    }
    vk = block_sum256(vk) * (1.f / DIMC);
    vr = block_sum256(vr) * (1.f / DIMC);
    float rk  = rsqrtf(vk + 1e-5f);
    float rr_ = rsqrtf(vr + 1e-5f);

    float ak = 0.f, ar = 0.f;
#pragma unroll
    for (int i = tid; i < N4; i += 256) {
        float4 a = sxk4[i], b = sxr4[i];
        float4 g1 = gk4[i], b1 = bk4[i], g2 = gr4[i], b2 = br4[i];
        float4 oa, ob;
        oa.x = (a.x - mk) * rk * g1.x + b1.x;   ob.x = (b.x - mr) * rr_ * g2.x + b2.x;
        oa.y = (a.y - mk) * rk * g1.y + b1.y;   ob.y = (b.y - mr) * rr_ * g2.y + b2.y;
        oa.z = (a.z - mk) * rk * g1.z + b1.z;   ob.z = (b.z - mr) * rr_ * g2.z + b2.z;
        oa.w = (a.w - mk) * rk * g1.w + b1.w;   ob.w = (b.w - mr) * rr_ * g2.w + b2.w;
        sxk4[i] = oa; sxr4[i] = ob;
        ak += (fabsf(oa.x) + fabsf(oa.y)) + (fabsf(oa.z) + fabsf(oa.w));
        ar += (fabsf(ob.x) + fabsf(ob.y)) + (fabsf(ob.z) + fabsf(ob.w));
    }
    float msk = block_sum256(ak) * (1.f / DIMC);
    float msr = block_sum256(ar) * (1.f / DIMC);
    float sclk = fmaxf(msk, 1e-8f) * (2.5f / 127.f);
    float sclr = fmaxf(msr, 1e-8f) * (2.5f / 127.f);

    float isclk = 1.f / sclk, isclr = 1.f / sclr;
    uint2* outk4 = (uint2*)(g_xkq + (size_t)row * DIMC);
    uint2* outr4 = (uint2*)(g_xrq + (size_t)row * DIMC);
#pragma unroll
    for (int i = tid; i < N4; i += 256) {
        float4 a = sxk4[i], b = sxr4[i];
        float qa0 = rintf(fminf(fmaxf(a.x * isclk, -127.f), 127.f));
        float qa1 = rintf(fminf(fmaxf(a.y * isclk, -127.f), 127.f));
        float qa2 = rintf(fminf(fmaxf(a.z * isclk, -127.f), 127.f));
        float qa3 = rintf(fminf(fmaxf(a.w * isclk, -127.f), 127.f));
        float qb0 = rintf(fminf(fmaxf(b.x * isclr, -127.f), 127.f));
        float qb1 = rintf(fminf(fmaxf(b.y * isclr, -127.f), 127.f));
        float qb2 = rintf(fminf(fmaxf(b.z * isclr, -127.f), 127.f));
        float qb3 = rintf(fminf(fmaxf(b.w * isclr, -127.f), 127.f));
        __nv_bfloat162 pk0 = __floats2bfloat162_rn(qa0, qa1);
        __nv_bfloat162 pk1 = __floats2bfloat162_rn(qa2, qa3);
        __nv_bfloat162 pr0 = __floats2bfloat162_rn(qb0, qb1);
        __nv_bfloat162 pr1 = __floats2bfloat162_rn(qb2, qb3);
        uint2 ok, orr;
        ok.x  = *(uint32_t*)&pk0;  ok.y  = *(uint32_t*)&pk1;
        orr.x = *(uint32_t*)&pr0;  orr.y = *(uint32_t*)&pr1;
        outk4[i] = ok;
        outr4[i] = orr;
    }
    if (tid == 0) { g_sk[row] = sclk; g_sr[row] = sclr; }
}

// ---------------------------------------------------------------------------
// LN + act-quant over k_act rows (bf16 out)
// ---------------------------------------------------------------------------
__global__ __launch_bounds__(256) void kact_ln_kernel(
    const float* __restrict__ gv, const float* __restrict__ bv)
{
    extern __shared__ __align__(16) float srow[];
    int row = blockIdx.x;
    int tid = threadIdx.x;
    const float4* in4 = (const float4*)(g_kact + (size_t)row * HID);
    float4* srow4 = (float4*)srow;
    const float4* gv4 = (const float4*)gv;
    const float4* bv4 = (const float4*)bv;
    const int N4 = HID / 4;

    float s = 0.f;
#pragma unroll
    for (int i = tid; i < N4; i += 256) {
        float4 v = in4[i];
        srow4[i] = v;
        s += (v.x + v.y) + (v.z + v.w);
    }
    float mu = block_sum256(s) * (1.f / HID);

    float vs = 0.f;
#pragma unroll
    for (int i = tid; i < N4; i += 256) {
        float4 v = srow4[i];
        float a0 = v.x - mu, a1 = v.y - mu, a2 = v.z - mu, a3 = v.w - mu;
        vs += (a0 * a0 + a1 * a1) + (a2 * a2 + a3 * a3);
    }
    float var = block_sum256(vs) * (1.f / HID);
    float rstd = rsqrtf(var + 1e-5f);

    float asum = 0.f;
#pragma unroll
    for (int i = tid; i < N4; i += 256) {
        float4 v = srow4[i];
        float4 g = gv4[i];
        float4 b = bv4[i];
        float4 a;
        a.x = (v.x - mu) * rstd * g.x + b.x;
        a.y = (v.y - mu) * rstd * g.y + b.y;
        a.z = (v.z - mu) * rstd * g.z + b.z;
        a.w = (v.w - mu) * rstd * g.w + b.w;
        srow4[i] = a;
        asum += (fabsf(a.x) + fabsf(a.y)) + (fabsf(a.z) + fabsf(a.w));
    }
    float ma = block_sum256(asum) * (1.f / HID);
    float scl = fmaxf(ma, 1e-8f) * (2.5f / 127.f);

    float iscl = 1.f / scl;
    uint2* out4 = (uint2*)(g_kq + (size_t)row * HID);
#pragma unroll
    for (int i = tid; i < N4; i += 256) {
        float4 a = srow4[i];
        float q0 = rintf(fminf(fmaxf(a.x * iscl, -127.f), 127.f));
        float q1 = rintf(fminf(fmaxf(a.y * iscl, -127.f), 127.f));
        float q2 = rintf(fminf(fmaxf(a.z * iscl, -127.f), 127.f));
        float q3 = rintf(fminf(fmaxf(a.w * iscl, -127.f), 127.f));
        __nv_bfloat162 p0 = __floats2bfloat162_rn(q0, q1);
        __nv_bfloat162 p1 = __floats2bfloat162_rn(q2, q3);
        uint2 o; o.x = *(uint32_t*)&p0; o.y = *(uint32_t*)&p1;
        out4[i] = o;
    }
    if (tid == 0) g_sv[row] = scl;
}

// ---------------------------------------------------------------------------
// Tiled bf16 mma.sync GEMM, 6-stage cp.async pipeline.
// CTA tile 256x128, 8 warps in 4x2 grid, warp tile 64x64.
//   C[m,n] = (sum_k A[m,k]*B[n,k]) * scaleA[m] * (*wsc), fused epilogue
// Epilogues: 0 = relu^2 (kact), 1 = sigmoid (gate), 2 = rg * val (output)
// ---------------------------------------------------------------------------
#define BMT 256
#define BNT 128
#define BKT 32
#define SST 40      // padded SMEM row stride (bf16 elems): 80 B/row
#define STAGES 6

template<int EPI>
__global__ __launch_bounds__(256, 1) void gemm_kernel(
    const __nv_bfloat16* __restrict__ A,    // [M, K] row-major
    const __nv_bfloat16* __restrict__ Bm,   // [N, K] row-major (K-major weights)
    const float* __restrict__ scaleA,       // [M]
    const float* __restrict__ wsc,          // pointer to scalar weight scale
    const float* __restrict__ rg,           // gate (EPI==2 only)
    float* __restrict__ C,                  // [M, ldc]
    int K, int ldc)
{
    extern __shared__ __align__(16) __nv_bfloat16 smem[];
    __nv_bfloat16* As = smem;                          // STAGES * BMT * SST
    __nv_bfloat16* Bs = smem + STAGES * BMT * SST;     // STAGES * BNT * SST

    int tid  = threadIdx.x;
    int m0   = blockIdx.y * BMT;
    int n0   = blockIdx.x * BNT;
    int warp = tid >> 5, lane = tid & 31;
    int wm = warp >> 1;      // 0..3 (64-row slices)
    int wn = warp & 1;       // 0..1 (64-col slices)

    float acc[4][8][4];
#pragma unroll
    for (int i = 0; i < 4; i++)
#pragma unroll
        for (int j = 0; j < 8; j++)
#pragma unroll
            for (int e = 0; e < 4; e++) acc[i][j][e] = 0.f;

    // loader: A 256 rows x 4 chunks(16B) = 1024, B 128 x 4 = 512; 6 chunks/thread
    const uint32_t stageA = BMT * SST * 2;   // 20480 B
    const uint32_t stageB = BNT * SST * 2;   // 10240 B
    uint32_t AsBase = smem_u32(As);
    uint32_t BsBase = smem_u32(Bs);

    int aRow[4], aCh[4];
#pragma unroll
    for (int t = 0; t < 4; t++) { int idx = tid + t * 256; aRow[t] = idx >> 2; aCh[t] = idx & 3; }
    int bRow[2], bCh[2];
#pragma unroll
    for (int t = 0; t < 2; t++) { int idx = tid + t * 256; bRow[t] = idx >> 2; bCh[t] = idx & 3; }

    const char* Agc = (const char*)(A  + (size_t)m0 * K);
    const char* Bgc = (const char*)(Bm + (size_t)n0 * K);
    const size_t rowB = (size_t)K * 2;

    auto load_tile = [&](int kt, int s) {
        size_t kOff = (size_t)kt * (BKT * 2);   // 64 bytes
        uint32_t sA = AsBase + (uint32_t)s * stageA;
        uint32_t sB = BsBase + (uint32_t)s * stageB;
#pragma unroll
        for (int t = 0; t < 4; t++)
            cp_async16(sA + (uint32_t)(aRow[t] * 80 + aCh[t] * 16),
                       Agc + (size_t)aRow[t] * rowB + kOff + aCh[t] * 16);
#pragma unroll
        for (int t = 0; t < 2; t++)
            cp_async16(sB + (uint32_t)(bRow[t] * 80 + bCh[t] * 16),
                       Bgc + (size_t)bRow[t] * rowB + kOff + bCh[t] * 16);
    };

    int KT = K / BKT;

#pragma unroll
    for (int s = 0; s < STAGES - 1; s++) { load_tile(s, s); cp_commit(); }

    int qr = lane & 7;
    int qg = lane >> 3;
    int l4 = lane & 15;

    for (int kt = 0; kt < KT; kt++) {
        cp_wait<STAGES - 2>();
        __syncthreads();

        int lt = kt + STAGES - 1;
        if (lt < KT) load_tile(lt, lt % STAGES);
        cp_commit();

        const __nv_bfloat16* Asb = As + (kt % STAGES) * (BMT * SST);
        const __nv_bfloat16* Bsb = Bs + (kt % STAGES) * (BNT * SST);

#pragma unroll
        for (int ks = 0; ks < 2; ks++) {
            uint32_t af[4][4];
            uint32_t bf[8][2];
#pragma unroll
            for (int mi = 0; mi < 4; mi++) {
                int r = wm * 64 + mi * 16 + qr + (qg & 1) * 8;
                int c = ks * 16 + (qg >> 1) * 8;
                uint32_t addr = smem_u32(&Asb[r * SST + c]);
                asm volatile(
                    "ldmatrix.sync.aligned.m8n8.x4.shared.b16 {%0,%1,%2,%3}, [%4];"
                    : "=r"(af[mi][0]), "=r"(af[mi][1]), "=r"(af[mi][2]), "=r"(af[mi][3])
                    : "r"(addr));
            }
#pragma unroll
            for (int ni = 0; ni < 8; ni++) {
                int r = wn * 64 + ni * 8 + (l4 & 7);
                int c = ks * 16 + (l4 >> 3) * 8;
                uint32_t addr = smem_u32(&Bsb[r * SST + c]);
                asm volatile(
                    "ldmatrix.sync.aligned.m8n8.x2.shared.b16 {%0,%1}, [%2];"
                    : "=r"(bf[ni][0]), "=r"(bf[ni][1])
                    : "r"(addr));
            }
#pragma unroll
            for (int mi = 0; mi < 4; mi++)
#pragma unroll
                for (int ni = 0; ni < 8; ni++) {
                    asm volatile(
                        "mma.sync.aligned.m16n8k16.row.col.f32.bf16.bf16.f32 "
                        "{%0,%1,%2,%3}, {%4,%5,%6,%7}, {%8,%9}, {%0,%1,%2,%3};"
                        : "+f"(acc[mi][ni][0]), "+f"(acc[mi][ni][1]),
                          "+f"(acc[mi][ni][2]), "+f"(acc[mi][ni][3])
                        : "r"(af[mi][0]), "r"(af[mi][1]), "r"(af[mi][2]), "r"(af[mi][3]),
                          "r"(bf[ni][0]), "r"(bf[ni][1]));
                }
        }
    }
    cp_wait<0>();

    // ---- fused epilogue ----
    float sw = *wsc;
    int rbase = m0 + wm * 64 + (lane >> 2);
    int cbase = n0 + wn * 64 + (lane & 3) * 2;
#pragma unroll
    for (int mi = 0; mi < 4; mi++) {
        int r0_ = rbase + mi * 16;
        float sA0 = scaleA[r0_]     * sw;
        float sA1 = scaleA[r0_ + 8] * sw;
#pragma unroll
        for (int ni = 0; ni < 8; ni++) {
            int c = cbase + ni * 8;
#pragma unroll
            for (int half = 0; half < 2; half++) {
                int rr = r0_ + half * 8;
                float sA = half ? sA1 : sA0;
                float v0 = acc[mi][ni][half * 2 + 0] * sA;
                float v1 = acc[mi][ni][half * 2 + 1] * sA;
                float2 ov;
                if (EPI == 0) {
                    float t0 = fmaxf(v0, 0.f), t1 = fmaxf(v1, 0.f);
                    ov.x = t0 * t0; ov.y = t1 * t1;
                } else if (EPI == 1) {
                    ov.x = 1.f / (1.f + expf(-v0));
                    ov.y = 1.f / (1.f + expf(-v1));
                } else {
                    float2 g2 = *(const float2*)(rg + (size_t)rr * ldc + c);
                    ov.x = g2.x * v0; ov.y = g2.y * v1;
                }
                *(float2*)(C + (size_t)rr * ldc + c) = ov;
            }
        }
    }
}

// ---------------------------------------------------------------------------
__global__ void state_copy_kernel(const float* __restrict__ x, float* __restrict__ out) {
    int i = blockIdx.x * 256 + threadIdx.x;
    if (i < BSZ * DIMC) {
        int b = i / DIMC, d = i % DIMC;
        out[i] = x[((size_t)b * SEQ + (SEQ - 1)) * DIMC + d];
    }
}

// ---------------------------------------------------------------------------
extern "C" void kernel_launch(void* const* d_in, const int* in_sizes, int n_in,
                              void* d_out, int out_size) {
    (void)in_sizes; (void)n_in;
    const float* x    = (const float*)d_in[0];
    const float* mu_k = (const float*)d_in[1];
    const float* mu_r = (const float*)d_in[2];
    const float* wk   = (const float*)d_in[3];
    const float* gk   = (const float*)d_in[4];
    const float* bk   = (const float*)d_in[5];
    const float* wr   = (const float*)d_in[6];
    const float* gr   = (const float*)d_in[7];
    const float* br   = (const float*)d_in[8];
    const float* wv   = (const float*)d_in[9];
    const float* gv   = (const float*)d_in[10];
    const float* bv   = (const float*)d_in[11];
    float* out = (float*)d_out;

    float *p_part, *p_wscale, *p_kact, *p_rg, *p_sk, *p_sr, *p_sv;
    __nv_bfloat16 *p_xkq, *p_xrq, *p_wkq, *p_wrq, *p_wvq, *p_kq;
    cudaGetSymbolAddress((void**)&p_part,   g_part);
    cudaGetSymbolAddress((void**)&p_wscale, g_wscale);
    cudaGetSymbolAddress((void**)&p_kact,   g_kact);
    cudaGetSymbolAddress((void**)&p_rg,     g_rg);
    cudaGetSymbolAddress((void**)&p_sk,     g_sk);
    cudaGetSymbolAddress((void**)&p_sr,     g_sr);
    cudaGetSymbolAddress((void**)&p_sv,     g_sv);
    cudaGetSymbolAddress((void**)&p_xkq,    g_xkq);
    cudaGetSymbolAddress((void**)&p_xrq,    g_xrq);
    cudaGetSymbolAddress((void**)&p_wkq,    g_wkq);
    cudaGetSymbolAddress((void**)&p_wrq,    g_wrq);
    cudaGetSymbolAddress((void**)&p_wvq,    g_wvq);
    cudaGetSymbolAddress((void**)&p_kq,     g_kq);

    const int smem_gemm = STAGES * (BMT + BNT) * SST * (int)sizeof(__nv_bfloat16); // 184320 B
    cudaFuncSetAttribute(gemm_kernel<0>, cudaFuncAttributeMaxDynamicSharedMemorySize, smem_gemm);
    cudaFuncSetAttribute(gemm_kernel<1>, cudaFuncAttributeMaxDynamicSharedMemorySize, smem_gemm);
    cudaFuncSetAttribute(gemm_kernel<2>, cudaFuncAttributeMaxDynamicSharedMemorySize, smem_gemm);

    abssum_kernel<<<512, 256>>>(wk, HID * DIMC,  p_part);
    abssum_kernel<<<512, 256>>>(wr, DIMC * DIMC, p_part + 512);
    abssum_kernel<<<512, 256>>>(wv, DIMC * HID,  p_part + 1024);
    wscale_fin_kernel<<<1, 256>>>();

    wquant_kernel<<<1024, 256>>>(wk, p_wkq, 0, HID * DIMC);
    wquant_kernel<<<256,  256>>>(wr, p_wrq, 1, DIMC * DIMC);
    wquant_kernel<<<1024, 256>>>(wv, p_wvq, 2, DIMC * HID);

    act_prep_kernel<<<MROWS, 256>>>(x, mu_k, mu_r, gk, bk, gr, br);

    // K GEMM (8192 x 8192 x 2048) with fused relu^2
    {
        dim3 g(HID / BNT, MROWS / BMT);
        gemm_kernel<0><<<g, 256, smem_gemm>>>(p_xkq, p_wkq, p_sk, p_wscale + 0,
                                              nullptr, p_kact, DIMC, HID);
    }

    kact_ln_kernel<<<MROWS, 256, HID * sizeof(float)>>>(gv, bv);

    // R GEMM (8192 x 2048 x 2048) with fused sigmoid
    {
        dim3 g(DIMC / BNT, MROWS / BMT);
        gemm_kernel<1><<<g, 256, smem_gemm>>>(p_xrq, p_wrq, p_sr, p_wscale + 1,
                                              nullptr, p_rg, DIMC, DIMC);
    }

    // V GEMM (8192 x 2048 x 8192) with fused gate multiply -> output
    {
        dim3 g(DIMC / BNT, MROWS / BMT);
        gemm_kernel<2><<<g, 256, smem_gemm>>>(p_kq, p_wvq, p_sv, p_wscale + 2,
                                              p_rg, out, HID, DIMC);
    }

    if (out_size >= MROWS * DIMC + BSZ * DIMC) {
        state_copy_kernel<<<(BSZ * DIMC + 255) / 256, 256>>>(
            x, out + (size_t)MROWS * DIMC);
    }
}